// round 17
// baseline (speedup 1.0000x reference)
#include <cuda_runtime.h>
#include <cuda_fp16.h>
#include <cstdint>
#include <math.h>

// ---------------- fixed problem shapes ----------------
#define N_TOK   32760          // 21 * 1560
#define DIM     1536
#define NHEADS  12
#define HD      128
#define S_SP    1560
#define N_T     21
#define ENC     768
#define NA      32
#define KV_ROWS 672
#define PKDIM   384            // NHEADS * NA
#define LOG2_10000 13.287712379549449f

// ---------------- scratch ----------------
__device__ __half g_xh[N_TOK * DIM];          // fp16 x
__device__ __half g_qwh[DIM * DIM];           // fp16 q_w
__device__ __half g_pwh[DIM * DIM];           // fp16 proj_w
__device__ __half g_ehsh[KV_ROWS * ENC];      // fp16 encoder states
__device__ __half g_kvwh[2 * DIM * ENC];      // fp16 kv_w
__device__ __half g_kh[KV_ROWS * DIM];        // RoPE'd k (fp16)
__device__ __half g_vh[KV_ROWS * DIM];        // v (fp16)
__device__ __half g_probsh[N_TOK * PKDIM];    // softmax probs [t*S+s][h*32+a]
__device__ __half g_w2h[N_T * DIM * PKDIM];   // W2^T [b][c][h*32+a]
__device__ float  g_pos[N_TOK];
__device__ float  g_mm[4];

// ---------------- helpers ----------------
__device__ __forceinline__ uint32_t smem_u32(const void* p) {
    uint32_t r;
    asm("{.reg .u64 t; cvta.to.shared.u64 t, %1; cvt.u32.u64 %0, t;}" : "=r"(r) : "l"(p));
    return r;
}

#define LDSM4(r0, r1, r2, r3, addr)                                            \
    asm volatile("ldmatrix.sync.aligned.m8n8.x4.shared.b16 {%0,%1,%2,%3}, [%4];" \
                 : "=r"(r0), "=r"(r1), "=r"(r2), "=r"(r3) : "r"(addr))

#define MMA_F16(d, a, b0, b1)                                                  \
    asm volatile("mma.sync.aligned.m16n8k16.row.col.f32.f16.f16.f32 "           \
                 "{%0,%1,%2,%3},{%4,%5,%6,%7},{%8,%9},{%0,%1,%2,%3};"          \
                 : "+f"(d[0]), "+f"(d[1]), "+f"(d[2]), "+f"(d[3])              \
                 : "r"(a[0]), "r"(a[1]), "r"(a[2]), "r"(a[3]), "r"(b0), "r"(b1))

// ---------------- fp32 -> fp16 conversion (4x ILP; for x) ----------------
__global__ void cvt_half_kernel(const float* __restrict__ in, __half* __restrict__ out, int n4) {
    int base = blockIdx.x * (blockDim.x * 4) + threadIdx.x;
    float4 v[4];
    bool ok[4];
#pragma unroll
    for (int g = 0; g < 4; g++) {
        int i = base + g * blockDim.x;
        ok[g] = (i < n4);
        if (ok[g]) v[g] = ((const float4*)in)[i];
    }
#pragma unroll
    for (int g = 0; g < 4; g++) {
        if (ok[g]) {
            int i = base + g * blockDim.x;
            __half2 h0 = __floats2half2_rn(v[g].x, v[g].y);
            __half2 h1 = __floats2half2_rn(v[g].z, v[g].w);
            uint2 pk;
            pk.x = *(uint32_t*)&h0;
            pk.y = *(uint32_t*)&h1;
            ((uint2*)out)[i] = pk;
        }
    }
}
#define CVT_GRID(n4) (((n4) + 1023) / 1024)

// ---------------- fused conversion of the 4 small tensors -----------------
#define SEG0 589824                   // q_w  (DIM*DIM/4)
#define SEG1 1179648                  // + p_w
#define SEG2 1308672                  // + ehs (KV_ROWS*ENC/4)
#define SEG3 1898496                  // + kv_w (2*DIM*ENC/4)
__global__ void cvt_weights_kernel(const float* __restrict__ q_w, const float* __restrict__ p_w,
                                   const float* __restrict__ ehs, const float* __restrict__ kv_w) {
    int base = blockIdx.x * 1024 + threadIdx.x;
#pragma unroll
    for (int g = 0; g < 4; g++) {
        int i = base + g * 256;
        const float* src;
        __half* dst;
        int off;
        if (i < SEG0)      { src = q_w;  dst = g_qwh;  off = i; }
        else if (i < SEG1) { src = p_w;  dst = g_pwh;  off = i - SEG0; }
        else if (i < SEG2) { src = ehs;  dst = g_ehsh; off = i - SEG1; }
        else if (i < SEG3) { src = kv_w; dst = g_kvwh; off = i - SEG2; }
        else continue;
        float4 v = ((const float4*)src)[off];
        __half2 h0 = __floats2half2_rn(v.x, v.y);
        __half2 h1 = __floats2half2_rn(v.z, v.w);
        uint2 pk;
        pk.x = *(uint32_t*)&h0;
        pk.y = *(uint32_t*)&h1;
        ((uint2*)dst)[off] = pk;
    }
}

// ---------------- min/max of attn-map rows (single CTA, float4) ----------------
__global__ void minmax_kernel(const float* __restrict__ m) {
    __shared__ float s0[512], s1[512], s2[512], s3[512];
    int tid = threadIdx.x;
    float mn0 = 1e30f, mx0 = -1e30f, mn1 = 1e30f, mx1 = -1e30f;
    const float4* m0v = (const float4*)m;
    const float4* m1v = (const float4*)(m + N_TOK);
    for (int i = tid; i < N_TOK / 4; i += 512) {
        float4 v0 = m0v[i], v1 = m1v[i];
        mn0 = fminf(mn0, fminf(fminf(v0.x, v0.y), fminf(v0.z, v0.w)));
        mx0 = fmaxf(mx0, fmaxf(fmaxf(v0.x, v0.y), fmaxf(v0.z, v0.w)));
        mn1 = fminf(mn1, fminf(fminf(v1.x, v1.y), fminf(v1.z, v1.w)));
        mx1 = fmaxf(mx1, fmaxf(fmaxf(v1.x, v1.y), fmaxf(v1.z, v1.w)));
    }
    s0[tid] = mn0; s1[tid] = mx0; s2[tid] = mn1; s3[tid] = mx1;
    __syncthreads();
    for (int off = 256; off > 0; off >>= 1) {
        if (tid < off) {
            s0[tid] = fminf(s0[tid], s0[tid + off]);
            s1[tid] = fmaxf(s1[tid], s1[tid + off]);
            s2[tid] = fminf(s2[tid], s2[tid + off]);
            s3[tid] = fmaxf(s3[tid], s3[tid + off]);
        }
        __syncthreads();
    }
    if (tid == 0) { g_mm[0] = s0[0]; g_mm[1] = s1[0]; g_mm[2] = s2[0]; g_mm[3] = s3[0]; }
}

// ---------------- routing positions ----------------
__global__ void pos_kernel(const float* __restrict__ m) {
    int n = blockIdx.x * blockDim.x + threadIdx.x;
    if (n >= N_TOK) return;
    float m0 = m[n], m1 = m[N_TOK + n];
    float r;
    if (m0 >= m1) r = (m0 - g_mm[0]) / (g_mm[1] - g_mm[0] + 1e-8f) * 4.0f;
    else          r = (m1 - g_mm[2]) / (g_mm[3] - g_mm[2] + 1e-8f) * 4.0f + 20.0f;
    g_pos[n] = r;
}

// ======== fp16 GEMM: CTA 128x128, 3-stage, occ 2 (kv + final) ========
#define KCHUNK  64
#define SSTAGES 3
#define SSM_SZ  16384
#define SSM_TOT (SSTAGES * 2 * SSM_SZ)          // 98304

__device__ __forceinline__ void fill_stage_s(
    const __half* __restrict__ A, const __half* __restrict__ B, int M, int K,
    int row0, int col0, int kt, uint32_t sA, uint32_t sB, int tid)
{
#pragma unroll
    for (int g = 0; g < 4; g++) {
        int ga = tid + g * 256;
        int row = ga >> 3, ch = ga & 7;
        uint32_t dst = sA + (uint32_t)row * 128u + (((uint32_t)ch * 16u) ^ (((uint32_t)row & 7u) << 4));
        const __half* src = A + (size_t)(row0 + row) * K + kt * KCHUNK + ch * 8;
        int sz = (row0 + row < M) ? 16 : 0;
        asm volatile("cp.async.cg.shared.global [%0], [%1], 16, %2;" :: "r"(dst), "l"(src), "r"(sz));
    }
#pragma unroll
    for (int g = 0; g < 4; g++) {
        int gb = tid + g * 256;
        int row = gb >> 3, ch = gb & 7;
        uint32_t dst = sB + (uint32_t)row * 128u + (((uint32_t)ch * 16u) ^ (((uint32_t)row & 7u) << 4));
        const __half* src = B + (size_t)(col0 + row) * K + kt * KCHUNK + ch * 8;
        asm volatile("cp.async.cg.shared.global [%0], [%1], 16;" :: "r"(dst), "l"(src));
    }
    asm volatile("cp.async.commit_group;");
}

// Generic GEMM (kv projection with fused RoPE split, final GEMM).
template <bool HALF_OUT, bool KV_EPI>
__global__ void __launch_bounds__(256, 2) gemm_f16_small(
    const __half* __restrict__ A, const __half* __restrict__ B,
    const float* __restrict__ bias, void* __restrict__ Cv,
    int M, int N, int K, size_t strA, size_t strB, size_t strC)
{
    extern __shared__ float smem[];
    const int tid  = threadIdx.x;
    const int lane = tid & 31, warp = tid >> 5;
    const int wm = warp >> 2, wn = warp & 3;
    const int row0 = blockIdx.y * 128, col0 = blockIdx.x * 128;

    A += (size_t)blockIdx.z * strA;
    B += (size_t)blockIdx.z * strB;

    const uint32_t sA = smem_u32(smem);
    const uint32_t sB = sA + SSTAGES * SSM_SZ;
    const int ktiles = K / KCHUNK;

    fill_stage_s(A, B, M, K, row0, col0, 0, sA, sB, tid);
    fill_stage_s(A, B, M, K, row0, col0, 1, sA + SSM_SZ, sB + SSM_SZ, tid);

    float acc[4][4][4];
#pragma unroll
    for (int i = 0; i < 4; i++)
#pragma unroll
        for (int j = 0; j < 4; j++)
#pragma unroll
            for (int k = 0; k < 4; k++) acc[i][j][k] = 0.0f;

    const int aRow = wm * 64 + ((lane >> 3) & 1) * 8 + (lane & 7);
    const int bRow = wn * 32 + ((lane >> 3) & 1) * 8 + (lane & 7);
    const uint32_t colSel = ((lane >> 4) & 1) * 16;
    const uint32_t xorv = ((uint32_t)lane & 7u) << 4;

    for (int it = 0; it < ktiles; it++) {
        if (it < ktiles - 1) asm volatile("cp.async.wait_group 1;" ::: "memory");
        else                 asm volatile("cp.async.wait_group 0;" ::: "memory");
        __syncthreads();
        const int st = it % 3;
        const uint32_t bA = sA + st * SSM_SZ;
        const uint32_t bB = sB + st * SSM_SZ;
        if (it + 2 < ktiles) {
            const int r = it + 2;
            fill_stage_s(A, B, M, K, row0, col0, r,
                         sA + (r % 3) * SSM_SZ, sB + (r % 3) * SSM_SZ, tid);
        }
#pragma unroll
        for (int ks = 0; ks < 4; ks++) {
            uint32_t a[4][4], bb[2][4];
            const uint32_t cb = ((uint32_t)(ks * 32) + colSel) ^ xorv;
#pragma unroll
            for (int mf = 0; mf < 4; mf++) {
                uint32_t ad = bA + (uint32_t)(aRow + mf * 16) * 128 + cb;
                LDSM4(a[mf][0], a[mf][1], a[mf][2], a[mf][3], ad);
            }
#pragma unroll
            for (int ng = 0; ng < 2; ng++) {
                uint32_t bd = bB + (uint32_t)(bRow + ng * 16) * 128 + cb;
                LDSM4(bb[ng][0], bb[ng][1], bb[ng][2], bb[ng][3], bd);
            }
#pragma unroll
            for (int mf = 0; mf < 4; mf++)
#pragma unroll
                for (int nf = 0; nf < 4; nf++) {
                    const int ng = nf >> 1, lo = nf & 1;
                    MMA_F16(acc[mf][nf], a[mf], bb[ng][lo], bb[ng][2 + lo]);
                }
        }
    }

#pragma unroll
    for (int mf = 0; mf < 4; mf++) {
        const int r0 = row0 + wm * 64 + mf * 16 + (lane >> 2);
        const int r8 = r0 + 8;
        float pos0 = 0.f, pos8 = 0.f;
        if (KV_EPI) {
            pos0 = ((r0 & 31) < 16) ? 2.0f : 22.0f;
            pos8 = ((r8 & 31) < 16) ? 2.0f : 22.0f;
        }
#pragma unroll
        for (int nf = 0; nf < 4; nf++) {
            const int c = col0 + wn * 32 + nf * 8 + (lane & 3) * 2;
            const float2 bv = *(const float2*)(bias + c);
            float o0 = acc[mf][nf][0] + bv.x;
            float o1 = acc[mf][nf][1] + bv.y;
            float o2 = acc[mf][nf][2] + bv.x;
            float o3 = acc[mf][nf][3] + bv.y;
            if (KV_EPI && c < DIM) {
                const int i = (c & 127) >> 1;
                const float fr = exp2f(-(float)i * (LOG2_10000 / 64.0f));
                float sn, cs;
                sincosf(pos0 * fr, &sn, &cs);
                float t0 = o0 * cs - o1 * sn;
                o1 = o1 * cs + o0 * sn; o0 = t0;
                sincosf(pos8 * fr, &sn, &cs);
                float t2 = o2 * cs - o3 * sn;
                o3 = o3 * cs + o2 * sn; o2 = t2;
            }
            if (KV_EPI) {
                if (c < DIM) {
                    if (r0 < M) *(__half2*)(g_kh + (size_t)r0 * DIM + c) = __floats2half2_rn(o0, o1);
                    if (r8 < M) *(__half2*)(g_kh + (size_t)r8 * DIM + c) = __floats2half2_rn(o2, o3);
                } else {
                    if (r0 < M) *(__half2*)(g_vh + (size_t)r0 * DIM + c - DIM) = __floats2half2_rn(o0, o1);
                    if (r8 < M) *(__half2*)(g_vh + (size_t)r8 * DIM + c - DIM) = __floats2half2_rn(o2, o3);
                }
            } else if (HALF_OUT) {
                __half* C = (__half*)Cv + (size_t)blockIdx.z * strC;
                if (r0 < M) *(__half2*)(C + (size_t)r0 * N + c) = __floats2half2_rn(o0, o1);
                if (r8 < M) *(__half2*)(C + (size_t)r8 * N + c) = __floats2half2_rn(o2, o3);
            } else {
                float* C = (float*)Cv + (size_t)blockIdx.z * strC;
                if (r0 < M) *(float2*)(C + (size_t)r0 * N + c) = make_float2(o0, o1);
                if (r8 < M) *(float2*)(C + (size_t)r8 * N + c) = make_float2(o2, o3);
            }
        }
    }
}

// ======== q GEMM 128x256 (2 heads/CTA), 3-stage, occ 1, fused scores ========
#define QSM_ASZ 16384
#define QSM_BSZ 32768
#define QSM_TOT (SSTAGES * (QSM_ASZ + QSM_BSZ))   // 147456

__device__ __forceinline__ void fill_stage_q(
    const __half* __restrict__ A, const __half* __restrict__ B,
    int row0, int col0, int kt, uint32_t sA, uint32_t sB, int tid)
{
#pragma unroll
    for (int g = 0; g < 4; g++) {                // A: 128 rows
        int ga = tid + g * 256;
        int row = ga >> 3, ch = ga & 7;
        uint32_t dst = sA + (uint32_t)row * 128u + (((uint32_t)ch * 16u) ^ (((uint32_t)row & 7u) << 4));
        const __half* src = A + (size_t)(row0 + row) * DIM + kt * KCHUNK + ch * 8;
        int sz = (row0 + row < N_TOK) ? 16 : 0;
        asm volatile("cp.async.cg.shared.global [%0], [%1], 16, %2;" :: "r"(dst), "l"(src), "r"(sz));
    }
#pragma unroll
    for (int g = 0; g < 8; g++) {                // B: 256 rows
        int gb = tid + g * 256;
        int row = gb >> 3, ch = gb & 7;
        uint32_t dst = sB + (uint32_t)row * 128u + (((uint32_t)ch * 16u) ^ (((uint32_t)row & 7u) << 4));
        const __half* src = B + (size_t)(col0 + row) * DIM + kt * KCHUNK + ch * 8;
        asm volatile("cp.async.cg.shared.global [%0], [%1], 16;" :: "r"(dst), "l"(src));
    }
    asm volatile("cp.async.commit_group;");
}

__global__ void __launch_bounds__(256, 1) gemm_q_scores(
    const __half* __restrict__ A, const __half* __restrict__ B,
    const float* __restrict__ bias)
{
    extern __shared__ float smem[];
    char* sbytes = (char*)smem;
    const int tid  = threadIdx.x;
    const int lane = tid & 31, warp = tid >> 5;
    const int wm = warp >> 2, wn = warp & 3;    // 2x4, warp tile 64x64
    const int row0 = blockIdx.y * 128;
    const int head0 = blockIdx.x * 2;
    const int col0 = head0 * 128;

    const uint32_t sA = smem_u32(smem);
    const uint32_t sB = sA + SSTAGES * QSM_ASZ;
    const int ktiles = DIM / KCHUNK;            // 24

    fill_stage_q(A, B, row0, col0, 0, sA, sB, tid);
    fill_stage_q(A, B, row0, col0, 1, sA + QSM_ASZ, sB + QSM_BSZ, tid);

    float acc[4][8][4];
#pragma unroll
    for (int i = 0; i < 4; i++)
#pragma unroll
        for (int j = 0; j < 8; j++)
#pragma unroll
            for (int k = 0; k < 4; k++) acc[i][j][k] = 0.0f;

    const int aRow = wm * 64 + ((lane >> 3) & 1) * 8 + (lane & 7);
    const int bRow = wn * 64 + ((lane >> 3) & 1) * 8 + (lane & 7);
    const uint32_t colSel = ((lane >> 4) & 1) * 16;
    const uint32_t xorv = ((uint32_t)lane & 7u) << 4;

    for (int it = 0; it < ktiles; it++) {
        if (it < ktiles - 1) asm volatile("cp.async.wait_group 1;" ::: "memory");
        else                 asm volatile("cp.async.wait_group 0;" ::: "memory");
        __syncthreads();
        const int st = it % 3;
        const uint32_t bA = sA + st * QSM_ASZ;
        const uint32_t bB = sB + st * QSM_BSZ;
        if (it + 2 < ktiles) {
            const int r = it + 2;
            fill_stage_q(A, B, row0, col0, r,
                         sA + (r % 3) * QSM_ASZ, sB + (r % 3) * QSM_BSZ, tid);
        }
#pragma unroll
        for (int ks = 0; ks < 4; ks++) {
            uint32_t a[4][4], bb[4][4];
            const uint32_t cb = ((uint32_t)(ks * 32) + colSel) ^ xorv;
#pragma unroll
            for (int mf = 0; mf < 4; mf++) {
                uint32_t ad = bA + (uint32_t)(aRow + mf * 16) * 128 + cb;
                LDSM4(a[mf][0], a[mf][1], a[mf][2], a[mf][3], ad);
            }
#pragma unroll
            for (int ng = 0; ng < 4; ng++) {
                uint32_t bd = bB + (uint32_t)(bRow + ng * 16) * 128 + cb;
                LDSM4(bb[ng][0], bb[ng][1], bb[ng][2], bb[ng][3], bd);
            }
#pragma unroll
            for (int mf = 0; mf < 4; mf++)
#pragma unroll
                for (int nf = 0; nf < 8; nf++) {
                    const int ng = nf >> 1, lo = nf & 1;
                    MMA_F16(acc[mf][nf], a[mf], bb[ng][lo], bb[ng][2 + lo]);
                }
        }
    }
    __syncthreads();   // mainloop smem dead; reuse below
    // layout: qtile[hh] at hh*32768 (2 kchunks x 16KB), ktile at 65536:
    //   65536 + hh*16384 + tl*8192 + kt*4096 (32 rows x 128B, swizzled)

    // ---- issue k-tile loads (2 heads x 2 frames) ----
    const int fA = row0 / S_SP;
    const int lastTok = (row0 + 127 < N_TOK) ? row0 + 127 : N_TOK - 1;
    const int fB = lastTok / S_SP;
    {
        const int fsel[2] = {fA, fB};
#pragma unroll
        for (int g = 0; g < 4; g++) {
            int i = tid + g * 256;
            int hh = i >> 9, tl = (i >> 8) & 1, row = (i >> 3) & 31, ch = i & 7;
            // row covers 32 rows x 8 ch = 256 per (hh,tl); need both kchunks:
            // split ch-space: g in 0..3 gives i in 0..1023 = 2hh x 2tl x 32row x 8ch (kt folded below)
            const __half* src0 = g_kh + (size_t)(fsel[tl] * 32 + row) * DIM + col0 + hh * 128 + ch * 8;
            uint32_t base = sA + 65536u + (uint32_t)hh * 16384u + (uint32_t)tl * 8192u;
            uint32_t sw = (((uint32_t)ch * 16u) ^ (((uint32_t)row & 7u) << 4));
            asm volatile("cp.async.cg.shared.global [%0], [%1], 16;"
                         :: "r"(base + (uint32_t)row * 128u + sw), "l"(src0));
            asm volatile("cp.async.cg.shared.global [%0], [%1], 16;"
                         :: "r"(base + 4096u + (uint32_t)row * 128u + sw), "l"(src0 + 64));
        }
        asm volatile("cp.async.commit_group;");
    }

    // ---- RoPE epilogue -> q smem (fp16, per-head K-major, swizzled) ----
#pragma unroll
    for (int mf = 0; mf < 4; mf++) {
        const int rr0 = wm * 64 + mf * 16 + (lane >> 2);
        const int rr8 = rr0 + 8;
        const int t0 = row0 + rr0, t8 = row0 + rr8;
        const float pos0 = g_pos[(t0 < N_TOK) ? t0 : (N_TOK - 1)];
        const float pos8 = g_pos[(t8 < N_TOK) ? t8 : (N_TOK - 1)];
#pragma unroll
        for (int nf = 0; nf < 8; nf++) {
            const int crel = wn * 64 + nf * 8 + (lane & 3) * 2;   // 0..255
            const float2 bv = *(const float2*)(bias + col0 + crel);
            float o0 = acc[mf][nf][0] + bv.x;
            float o1 = acc[mf][nf][1] + bv.y;
            float o2 = acc[mf][nf][2] + bv.x;
            float o3 = acc[mf][nf][3] + bv.y;
            const int hc128 = crel & 127;           // head-local col
            const int i = hc128 >> 1;
            const float fr = exp2f(-(float)i * (LOG2_10000 / 64.0f));
            float sn, cs;
            sincosf(pos0 * fr, &sn, &cs);
            float tt = o0 * cs - o1 * sn;
            o1 = o1 * cs + o0 * sn; o0 = tt;
            sincosf(pos8 * fr, &sn, &cs);
            tt = o2 * cs - o3 * sn;
            o3 = o3 * cs + o2 * sn; o2 = tt;
            const int hh = crel >> 7;
            const int kt = (hc128 >> 6), hc = hc128 & 63;
            uint32_t base = (uint32_t)hh * 32768u + (uint32_t)kt * 16384u;
            uint32_t off0 = base + (uint32_t)rr0 * 128u + (((uint32_t)hc * 2u) ^ (((uint32_t)rr0 & 7u) << 4));
            uint32_t off8 = base + (uint32_t)rr8 * 128u + (((uint32_t)hc * 2u) ^ (((uint32_t)rr8 & 7u) << 4));
            *(__half2*)(sbytes + off0) = __floats2half2_rn(o0, o1);
            *(__half2*)(sbytes + off8) = __floats2half2_rn(o2, o3);
        }
    }
    asm volatile("cp.async.wait_group 0;" ::: "memory");
    __syncthreads();

    // ---- score MMA: warp w -> tokens w*16..+15, both heads, 2 frame key-sets ----
    const int aRow2 = warp * 16 + ((lane >> 3) & 1) * 8 + (lane & 7);
    const int bRow2 = ((lane >> 3) & 1) * 8 + (lane & 7);
    const int rA = lane >> 2;
    const int tok0 = row0 + warp * 16 + rA;
    const int tok8 = tok0 + 8;
    const int base0 = (tok0 / S_SP == fA) ? 0 : 4;
    const int base8 = (tok8 / S_SP == fA) ? 0 : 4;
    const float scl = 0.08838834764831845f;

#pragma unroll
    for (int hh = 0; hh < 2; hh++) {
        float sacc[8][4];
#pragma unroll
        for (int i = 0; i < 8; i++)
#pragma unroll
            for (int j = 0; j < 4; j++) sacc[i][j] = 0.0f;

        const uint32_t qb = sA + (uint32_t)hh * 32768u;
        const uint32_t kb = sA + 65536u + (uint32_t)hh * 16384u;
#pragma unroll
        for (int kf = 0; kf < 8; kf++) {
            const uint32_t cb = ((uint32_t)((kf & 3) * 32) + colSel) ^ xorv;
            uint32_t a0, a1, a2, a3;
            LDSM4(a0, a1, a2, a3, qb + (uint32_t)(kf >> 2) * 16384u + (uint32_t)aRow2 * 128u + cb);
            uint32_t afrag[4] = {a0, a1, a2, a3};
#pragma unroll
            for (int tl = 0; tl < 2; tl++) {
#pragma unroll
                for (int ng = 0; ng < 2; ng++) {
                    uint32_t b0, b1, b2, b3;
                    uint32_t bd = kb + (uint32_t)tl * 8192u + (uint32_t)(kf >> 2) * 4096u +
                                  (uint32_t)(ng * 16 + bRow2) * 128u + cb;
                    LDSM4(b0, b1, b2, b3, bd);
                    MMA_F16(sacc[tl * 4 + ng * 2 + 0], afrag, b0, b2);
                    MMA_F16(sacc[tl * 4 + ng * 2 + 1], afrag, b1, b3);
                }
            }
        }

        // softmax over this head's 32 keys
        float e0[8], e8[8];
        float mx0 = -1e30f, mx8 = -1e30f;
#pragma unroll
        for (int nf = 0; nf < 4; nf++) {
            mx0 = fmaxf(mx0, fmaxf(sacc[base0 + nf][0], sacc[base0 + nf][1]));
            mx8 = fmaxf(mx8, fmaxf(sacc[base8 + nf][2], sacc[base8 + nf][3]));
        }
        mx0 = fmaxf(mx0, __shfl_xor_sync(0xFFFFFFFFu, mx0, 1));
        mx8 = fmaxf(mx8, __shfl_xor_sync(0xFFFFFFFFu, mx8, 1));
        mx0 = fmaxf(mx0, __shfl_xor_sync(0xFFFFFFFFu, mx0, 2));
        mx8 = fmaxf(mx8, __shfl_xor_sync(0xFFFFFFFFu, mx8, 2));
        mx0 *= scl; mx8 *= scl;

        float s0 = 0.f, s8 = 0.f;
#pragma unroll
        for (int nf = 0; nf < 4; nf++) {
            e0[nf * 2 + 0] = __expf(sacc[base0 + nf][0] * scl - mx0);
            e0[nf * 2 + 1] = __expf(sacc[base0 + nf][1] * scl - mx0);
            e8[nf * 2 + 0] = __expf(sacc[base8 + nf][2] * scl - mx8);
            e8[nf * 2 + 1] = __expf(sacc[base8 + nf][3] * scl - mx8);
            s0 += e0[nf * 2] + e0[nf * 2 + 1];
            s8 += e8[nf * 2] + e8[nf * 2 + 1];
        }
        s0 += __shfl_xor_sync(0xFFFFFFFFu, s0, 1);
        s8 += __shfl_xor_sync(0xFFFFFFFFu, s8, 1);
        s0 += __shfl_xor_sync(0xFFFFFFFFu, s0, 2);
        s8 += __shfl_xor_sync(0xFFFFFFFFu, s8, 2);
        const float inv0 = 1.0f / s0, inv8 = 1.0f / s8;

        const int head = head0 + hh;
#pragma unroll
        for (int nf = 0; nf < 4; nf++) {
            const int ck = nf * 8 + (lane & 3) * 2;
            if (tok0 < N_TOK)
                *(__half2*)(g_probsh + (size_t)tok0 * PKDIM + head * NA + ck) =
                    __floats2half2_rn(e0[nf * 2] * inv0, e0[nf * 2 + 1] * inv0);
            if (tok8 < N_TOK)
                *(__half2*)(g_probsh + (size_t)tok8 * PKDIM + head * NA + ck) =
                    __floats2half2_rn(e8[nf * 2] * inv8, e8[nf * 2 + 1] * inv8);
        }
    }
}

// ---------------- W2 fold on tensor cores ------------------------------------
__global__ void __launch_bounds__(128) w2_mma_kernel() {
    const int mt = blockIdx.x;
    const int h  = blockIdx.y;
    const int b  = blockIdx.z;
    __shared__ __align__(16) char smem[2 * 16384 + 2 * 4096];

    const int tid = threadIdx.x;
    const int lane = tid & 31, warp = tid >> 5;
    const uint32_t sA = smem_u32(smem);
    const uint32_t sB = sA + 2 * 16384;

#pragma unroll
    for (int g = 0; g < 16; g++) {
        int i = tid + g * 128;
        int kt = i >> 10, row = (i >> 3) & 127, ch = i & 7;
        uint32_t dst = sA + kt * 16384 + (uint32_t)row * 128u +
                       (((uint32_t)ch * 16u) ^ (((uint32_t)row & 7u) << 4));
        const __half* src = g_pwh + (size_t)(mt * 128 + row) * DIM + h * HD + kt * KCHUNK + ch * 8;
        asm volatile("cp.async.cg.shared.global [%0], [%1], 16;" :: "r"(dst), "l"(src));
    }
#pragma unroll
    for (int g = 0; g < 4; g++) {
        int i = tid + g * 128;
        int kt = i >> 8, row = (i >> 3) & 31, ch = i & 7;
        uint32_t dst = sB + kt * 4096 + (uint32_t)row * 128u +
                       (((uint32_t)ch * 16u) ^ (((uint32_t)row & 7u) << 4));
        const __half* src = g_vh + (size_t)(b * 32 + row) * DIM + h * HD + kt * KCHUNK + ch * 8;
        asm volatile("cp.async.cg.shared.global [%0], [%1], 16;" :: "r"(dst), "l"(src));
    }
    asm volatile("cp.async.commit_group;");
    asm volatile("cp.async.wait_group 0;" ::: "memory");
    __syncthreads();

    float acc[2][4][4];
#pragma unroll
    for (int i = 0; i < 2; i++)
#pragma unroll
        for (int j = 0; j < 4; j++)
#pragma unroll
            for (int k = 0; k < 4; k++) acc[i][j][k] = 0.0f;

    const int aRow = warp * 32 + ((lane >> 3) & 1) * 8 + (lane & 7);
    const int bRow = ((lane >> 3) & 1) * 8 + (lane & 7);
    const uint32_t colSel = ((lane >> 4) & 1) * 16;
    const uint32_t xorv = ((uint32_t)lane & 7u) << 4;

#pragma unroll
    for (int kt = 0; kt < 2; kt++) {
        const uint32_t bA = sA + kt * 16384;
        const uint32_t bB = sB + kt * 4096;
#pragma unroll
        for (int ks = 0; ks < 4; ks++) {
            uint32_t a[2][4], bb[2][4];
            const uint32_t cb = ((uint32_t)(ks * 32) + colSel) ^ xorv;
#pragma unroll
            for (int mf = 0; mf < 2; mf++) {
                uint32_t ad = bA + (uint32_t)(aRow + mf * 16) * 128 + cb;
                LDSM4(a[mf][0], a[mf][1], a[mf][2], a[mf][3], ad);
            }
#pragma unroll
            for (int ng = 0; ng < 2; ng++) {
                uint32_t bd = bB + (uint32_t)(bRow + ng * 16) * 128 + cb;
                LDSM4(bb[ng][0], bb[ng][1], bb[ng][2], bb[ng][3], bd);
            }
#pragma unroll
            for (int mf = 0; mf < 2; mf++)
#pragma unroll
                for (int nf = 0; nf < 4; nf++) {
                    const int ng = nf >> 1, lo = nf & 1;
                    MMA_F16(acc[mf][nf], a[mf], bb[ng][lo], bb[ng][2 + lo]);
                }
        }
    }

    __half* dst = g_w2h + (size_t)b * DIM * PKDIM + h * NA;
#pragma unroll
    for (int mf = 0; mf < 2; mf++) {
        const int r0 = mt * 128 + warp * 32 + mf * 16 + (lane >> 2);
        const int r8 = r0 + 8;
#pragma unroll
        for (int nf = 0; nf < 4; nf++) {
            const int c = nf * 8 + (lane & 3) * 2;
            *(__half2*)(dst + (size_t)r0 * PKDIM + c) = __floats2half2_rn(acc[mf][nf][0], acc[mf][nf][1]);
            *(__half2*)(dst + (size_t)r8 * PKDIM + c) = __floats2half2_rn(acc[mf][nf][2], acc[mf][nf][3]);
        }
    }
}

// ---------------- launch (single stream) ----------------
extern "C" void kernel_launch(void* const* d_in, const int* in_sizes, int n_in,
                              void* d_out, int out_size)
{
    const float* x    = (const float*)d_in[0];
    const float* ehs  = (const float*)d_in[1];
    const float* amap = (const float*)d_in[2];
    const float* q_w  = (const float*)d_in[3];
    const float* q_b  = (const float*)d_in[4];
    const float* kv_w = (const float*)d_in[5];
    const float* kv_b = (const float*)d_in[6];
    const float* p_w  = (const float*)d_in[7];
    const float* p_b  = (const float*)d_in[8];
    float* out = (float*)d_out;

    __half *xh, *qwh, *kvwh, *ehsh, *probsh, *w2h;
    cudaGetSymbolAddress((void**)&xh,     g_xh);
    cudaGetSymbolAddress((void**)&qwh,    g_qwh);
    cudaGetSymbolAddress((void**)&kvwh,   g_kvwh);
    cudaGetSymbolAddress((void**)&ehsh,   g_ehsh);
    cudaGetSymbolAddress((void**)&probsh, g_probsh);
    cudaGetSymbolAddress((void**)&w2h,    g_w2h);

    cudaFuncSetAttribute((const void*)gemm_q_scores,
                         cudaFuncAttributeMaxDynamicSharedMemorySize, QSM_TOT);
    cudaFuncSetAttribute((const void*)gemm_f16_small<false, false>,
                         cudaFuncAttributeMaxDynamicSharedMemorySize, SSM_TOT);
    cudaFuncSetAttribute((const void*)gemm_f16_small<false, true>,
                         cudaFuncAttributeMaxDynamicSharedMemorySize, SSM_TOT);

    // routing positions
    minmax_kernel<<<1, 512>>>(amap);
    pos_kernel<<<(N_TOK + 255) / 256, 256>>>(amap);

    // fp16 conversions
    cvt_half_kernel<<<CVT_GRID(N_TOK * DIM / 4), 256>>>(x, xh, N_TOK * DIM / 4);
    cvt_weights_kernel<<<(SEG3 + 1023) / 1024, 256>>>(q_w, p_w, ehs, kv_w);

    // kv projection with fused split + RoPE(k): k -> fp16 g_kh, v -> fp16 g_vh
    gemm_f16_small<false, true><<<dim3((2 * DIM) / 128, (KV_ROWS + 127) / 128, 1), 256, SSM_TOT>>>(
        ehsh, kvwh, kv_b, nullptr, KV_ROWS, 2 * DIM, ENC, 0, 0, 0);

    // q GEMM (2 heads/CTA) + fused RoPE + scores + softmax -> probs
    gemm_q_scores<<<dim3(NHEADS / 2, (N_TOK + 127) / 128), 256, QSM_TOT>>>(xh, qwh, q_b);

    // W2 = V @ proj (tensor cores) -> fp16
    w2_mma_kernel<<<dim3(DIM / 128, NHEADS, N_T), 128>>>();

    // out[b] = probs[b] @ W2[b]^T + p_b   (batched, K=384)
    gemm_f16_small<false, false><<<dim3(DIM / 128, (S_SP + 127) / 128, N_T), 256, SSM_TOT>>>(
        probsh, w2h, p_b, out, S_SP, DIM, PKDIM,
        (size_t)S_SP * PKDIM, (size_t)DIM * PKDIM, (size_t)S_SP * DIM);
}